// round 11
// baseline (speedup 1.0000x reference)
#include <cuda_runtime.h>

#define NS 4096
#define NB 64
#define FUSED_BLOCKS 192   // >= sum ceil(cnt_i/32) <= 64 + 128
typedef unsigned long long u64;

// f32x2 packed math (sm_103a): one FFMA2 = 2 fp32 FMAs
#define PACKDUP(d, x)  asm("mov.b64 %0, {%1, %1};" : "=l"(d) : "f"(x))
#define FFMA2(d, a, b) asm("fma.rn.f32x2 %0, %1, %2, %0;" : "+l"(d) : "l"(a), "l"(b))
#define UNPACK64(lo, hi, v) asm("mov.b64 {%0, %1}, %2;" : "=f"(lo), "=f"(hi) : "l"(v))

// ---- scratch (device globals: no allocation allowed) ----
__device__ float g_P[512 * 256];     // prefix table  (c0,c1,c2)
__device__ float g_S[512 * 256];     // suffix table  (c5,c6,c7)
__device__ int   g_p[NS];
__device__ int   g_q[NS];
__device__ int   g_cnt[NB];          // zero-init at load; ticket re-zeros each run
__device__ int   g_bkt[NB * NS];     // sample ids per (d3,d4) bucket
__device__ int   g_done;             // ticket counter for cleanup

// ---------------------------------------------------------------------------
// Fused setup: blocks 0-31 prefix GEMMs, 32-63 suffix GEMMs, 64-79 decode.
__global__ void __launch_bounds__(256) k_setup(
    const float* __restrict__ c0, const float* __restrict__ c1,
    const float* __restrict__ c2, const float* __restrict__ c5,
    const float* __restrict__ c6, const float* __restrict__ c7,
    const int*   __restrict__ coords)
{
    __shared__ float sA[64 * 68];
    __shared__ float sB[64 * 68];
    int bid = blockIdx.x;
    int tid = threadIdx.x;

    if (bid < 32) {
        // ---------------- prefix: P[(ab,c)][col] = T[ab] @ core2[:,c,col] ----
        int cdig = bid >> 2, col0 = (bid & 3) * 64;
        for (int e = tid; e < 4096; e += 256) {
            int r = e >> 6, ab = e & 63;
            int a = ab >> 3, b = ab & 7;
            float acc = 0.f;
#pragma unroll
            for (int i = 0; i < 8; i++)
                acc += c0[a * 8 + i] * c1[(i * 8 + b) * 64 + r];
            sA[r * 68 + ab] = acc;
        }
        for (int e = tid; e < 4096; e += 256) {
            int r = e >> 6, cc = e & 63;
            sB[r * 68 + cc] = c2[(r * 8 + cdig) * 256 + col0 + cc];
        }
        __syncthreads();
        int ct = tid & 15, abt = tid >> 4;
        float acc[4][4] = {};
        for (int r = 0; r < 64; r++) {
            float4 tv = *(const float4*)&sA[r * 68 + abt * 4];
            float4 bv = *(const float4*)&sB[r * 68 + ct * 4];
            acc[0][0] += tv.x * bv.x; acc[0][1] += tv.x * bv.y; acc[0][2] += tv.x * bv.z; acc[0][3] += tv.x * bv.w;
            acc[1][0] += tv.y * bv.x; acc[1][1] += tv.y * bv.y; acc[1][2] += tv.y * bv.z; acc[1][3] += tv.y * bv.w;
            acc[2][0] += tv.z * bv.x; acc[2][1] += tv.z * bv.y; acc[2][2] += tv.z * bv.z; acc[2][3] += tv.z * bv.w;
            acc[3][0] += tv.w * bv.x; acc[3][1] += tv.w * bv.y; acc[3][2] += tv.w * bv.z; acc[3][3] += tv.w * bv.w;
        }
#pragma unroll
        for (int ii = 0; ii < 4; ii++) {
            int p = (abt * 4 + ii) * 8 + cdig;
            *(float4*)&g_P[p * 256 + col0 + ct * 4] =
                make_float4(acc[ii][0], acc[ii][1], acc[ii][2], acc[ii][3]);
        }
    } else if (bid < 64) {
        // ---------------- suffix: S[(a,bc)][row] = core5[row,a,:] @ U[bc] ----
        int b2 = bid - 32;
        int adig = b2 >> 2, row0 = (b2 & 3) * 64;
        for (int e = tid; e < 4096; e += 256) {
            int r = e >> 6, j = e & 63;
            sA[j * 68 + r] = c5[((row0 + r) * 8 + adig) * 64 + j];
        }
        for (int e = tid; e < 4096; e += 256) {
            int j = e >> 6, bc = e & 63;
            int b = bc >> 3, c = bc & 7;
            float acc = 0.f;
#pragma unroll
            for (int i = 0; i < 8; i++)
                acc += c6[(j * 8 + b) * 8 + i] * c7[i * 8 + c];
            sB[j * 68 + bc] = acc;
        }
        __syncthreads();
        int rt = tid & 15, bct = tid >> 4;
        float acc[4][4] = {};
        for (int j = 0; j < 64; j++) {
            float4 av = *(const float4*)&sA[j * 68 + rt * 4];
            float4 uv = *(const float4*)&sB[j * 68 + bct * 4];
            acc[0][0] += av.x * uv.x; acc[0][1] += av.x * uv.y; acc[0][2] += av.x * uv.z; acc[0][3] += av.x * uv.w;
            acc[1][0] += av.y * uv.x; acc[1][1] += av.y * uv.y; acc[1][2] += av.y * uv.z; acc[1][3] += av.y * uv.w;
            acc[2][0] += av.z * uv.x; acc[2][1] += av.z * uv.y; acc[2][2] += av.z * uv.z; acc[2][3] += av.z * uv.w;
            acc[3][0] += av.w * uv.x; acc[3][1] += av.w * uv.y; acc[3][2] += av.w * uv.z; acc[3][3] += av.w * uv.w;
        }
#pragma unroll
        for (int jj = 0; jj < 4; jj++) {
            int q = adig * 64 + bct * 4 + jj;
            *(float4*)&g_S[q * 256 + row0 + rt * 4] =
                make_float4(acc[0][jj], acc[1][jj], acc[2][jj], acc[3][jj]);
        }
    } else {
        // ---------------- decode: bucket by (d3,d4) pair ----------------
        int n = (bid - 64) * 256 + tid;
        if (n < NS) {
            int x = coords[3 * n], y = coords[3 * n + 1], z = coords[3 * n + 2];
            int d[8];
#pragma unroll
            for (int l = 0; l < 8; l++) {
                int sh = 7 - l;
                d[l] = 4 * ((x >> sh) & 1) + 2 * ((y >> sh) & 1) + ((z >> sh) & 1);
            }
            g_p[n] = d[0] * 64 + d[1] * 8 + d[2];
            g_q[n] = d[5] * 64 + d[6] * 8 + d[7];
            int bkt = d[3] * 8 + d[4];
            int pos = atomicAdd(&g_cnt[bkt], 1);
            g_bkt[bkt * NS + pos] = n;
        }
    }
}

// ---------------------------------------------------------------------------
// Fused both-levels kernel. 128 threads, 32-sample tile, bucket = (d3,d4).
//   GEMM1: V[32x256] = P-rows @ core3[:,d3,:]   (V kept in smem, row-major)
//   GEMM2: out2[32x256] = V @ core4[:,d4,:], dotted with S rows on the fly.
// Column halves processed sequentially (Bs reused). K chunks of 32 rows with
// gmem->reg prefetch overlapping smem compute.
// Smem: Ast[256][32] 32KB | Bs[32][128] 16KB | Vst[32][260] 32.5KB = 80.5KB.

__device__ __forceinline__ int2 tile_map64(int t) {
    int acc = 0, c = -1, base = 0;
    for (int i = 0; i < NB; i++) {
        int tiles = (g_cnt[i] + 31) >> 5;
        if (c < 0 && t < acc + tiles) { c = i; base = (t - acc) * 32; }
        acc += tiles;
    }
    return make_int2(c, base);
}

#define LDB(BG, KC)                                                            \
    {                                                                          \
        _Pragma("unroll")                                                      \
        for (int p4 = 0; p4 < 8; p4++)                                         \
            nb[p4] = __ldg((const float4*)(BG + ((KC) * 32 + p4 * 4 + brow) * 2048 + bcol)); \
    }
#define STB()                                                                  \
    {                                                                          \
        _Pragma("unroll")                                                      \
        for (int p4 = 0; p4 < 8; p4++)                                         \
            *(float4*)&Bs[(p4 * 4 + brow) * 128 + bcol] = nb[p4];              \
    }

// GEMM1 chunk: A sample-pairs packed from Ast[k][s]; 16 FFMA2 / 23 instr.
#define CHUNK1(KC)                                                             \
    {                                                                          \
        _Pragma("unroll 8")                                                    \
        for (int kk = 0; kk < 32; kk++) {                                      \
            float4 b = *(const float4*)&Bs[kk * 128 + colg * 4];               \
            u64 bd0, bd1, bd2, bd3;                                            \
            PACKDUP(bd0, b.x); PACKDUP(bd1, b.y);                              \
            PACKDUP(bd2, b.z); PACKDUP(bd3, b.w);                              \
            const u64* ap = (const u64*)&Ast[((KC) * 32 + kk) * 32 + sg * 8];  \
            u64 a0 = ap[0], a1 = ap[1], a2 = ap[2], a3 = ap[3];                \
            FFMA2(acc[0][0], a0, bd0); FFMA2(acc[0][1], a0, bd1);              \
            FFMA2(acc[0][2], a0, bd2); FFMA2(acc[0][3], a0, bd3);              \
            FFMA2(acc[1][0], a1, bd0); FFMA2(acc[1][1], a1, bd1);              \
            FFMA2(acc[1][2], a1, bd2); FFMA2(acc[1][3], a1, bd3);              \
            FFMA2(acc[2][0], a2, bd0); FFMA2(acc[2][1], a2, bd1);              \
            FFMA2(acc[2][2], a2, bd2); FFMA2(acc[2][3], a2, bd3);              \
            FFMA2(acc[3][0], a3, bd0); FFMA2(acc[3][1], a3, bd1);              \
            FFMA2(acc[3][2], a3, bd2); FFMA2(acc[3][3], a3, bd3);              \
        }                                                                      \
    }

// GEMM2 chunk: A = broadcast scalar V[s][k] (dup), B = natural u64 col-pairs.
#define CHUNK2(KC)                                                             \
    {                                                                          \
        _Pragma("unroll 8")                                                    \
        for (int kk = 0; kk < 32; kk++) {                                      \
            const u64* bp = (const u64*)&Bs[kk * 128 + colg * 4];              \
            u64 b01 = bp[0], b23 = bp[1];                                      \
            _Pragma("unroll")                                                  \
            for (int i = 0; i < 8; i++) {                                      \
                float av = Vst[(sg * 8 + i) * 260 + (KC) * 32 + kk];           \
                u64 ad; PACKDUP(ad, av);                                       \
                FFMA2(acc2[i][0], ad, b01);                                    \
                FFMA2(acc2[i][1], ad, b23);                                    \
            }                                                                  \
        }                                                                      \
    }

#define GEMM_PASS(BG, CHUNK)                                                   \
    LDB(BG, 0); STB(); __syncthreads();                                        \
    for (int kc = 0; kc < 8; kc++) {                                           \
        if (kc < 7) LDB(BG, kc + 1);                                           \
        CHUNK(kc);                                                             \
        __syncthreads();                                                       \
        if (kc < 7) { STB(); __syncthreads(); }                                \
    }

__global__ void __launch_bounds__(128) k_fused(const float* __restrict__ B3,
                                               const float* __restrict__ B4,
                                               float* __restrict__ out) {
    extern __shared__ float smem[];
    float* Ast = smem;                  // [k 0..255][s 0..31]
    float* Bs  = smem + 8192;           // [32][128]
    float* Vst = smem + 8192 + 4096;    // [s 0..31][260]

    int tid = threadIdx.x;
    int2 cb = tile_map64(blockIdx.x);
    int c = cb.x, base = cb.y;
    int cnt = (c >= 0) ? g_cnt[c] : 0;
    __syncthreads();   // all threads finished reading g_cnt
    if (tid == 0) {
        int old = atomicAdd(&g_done, 1);
        if (old == FUSED_BLOCKS - 1) {   // last arrival: safe to clean
            for (int j = 0; j < NB; j++) g_cnt[j] = 0;
            g_done = 0;
        }
    }
    if (c < 0) return;
    int c3 = c >> 3, c4 = c & 7;

    // ---- stage A transposed: thread owns sample s = tid&31 ----
    {
        int s = tid & 31;
        int li = base + s;
        int rsel = -1;
        if (li < cnt) rsel = g_p[g_bkt[c * NS + li]];
#pragma unroll
        for (int pass = 0; pass < 16; pass++) {
            int kq = (tid >> 5) + 4 * pass;
            float4 v = make_float4(0.f, 0.f, 0.f, 0.f);
            if (rsel >= 0) v = __ldg((const float4*)(g_P + rsel * 256 + kq * 4));
            Ast[(kq * 4 + 0) * 32 + s] = v.x;
            Ast[(kq * 4 + 1) * 32 + s] = v.y;
            Ast[(kq * 4 + 2) * 32 + s] = v.z;
            Ast[(kq * 4 + 3) * 32 + s] = v.w;
        }
    }
    __syncthreads();

    int colg = tid & 31, sg = tid >> 5;
    int brow = tid >> 5, bcol = (tid & 31) * 4;
    float4 nb[8];

    // ---- GEMM1: two column halves -> Vst ----
    const float* Bg3 = B3 + c3 * 256;
#pragma unroll 1
    for (int h = 0; h < 2; h++) {
        const float* BG = Bg3 + h * 128;
        u64 acc[4][4] = {};
        GEMM_PASS(BG, CHUNK1);
#pragma unroll
        for (int p = 0; p < 4; p++) {
            float lo0, lo1, lo2, lo3, hi0, hi1, hi2, hi3;
            UNPACK64(lo0, hi0, acc[p][0]); UNPACK64(lo1, hi1, acc[p][1]);
            UNPACK64(lo2, hi2, acc[p][2]); UNPACK64(lo3, hi3, acc[p][3]);
            int s0 = sg * 8 + 2 * p, s1 = s0 + 1;
            *(float4*)&Vst[s0 * 260 + h * 128 + colg * 4] = make_float4(lo0, lo1, lo2, lo3);
            *(float4*)&Vst[s1 * 260 + h * 128 + colg * 4] = make_float4(hi0, hi1, hi2, hi3);
        }
        __syncthreads();   // Bs reuse + (after h=1) Vst complete
    }

    // ---- GEMM2 + suffix dot: two column halves, accumulate part ----
    // sample ids / suffix rows for this thread's 8 samples
    int qrow[8];
#pragma unroll
    for (int i = 0; i < 8; i++) {
        int l = base + sg * 8 + i;
        qrow[i] = (l < cnt) ? g_q[g_bkt[c * NS + l]] : 0;
    }
    float part[8] = {};
    const float* Bg4 = B4 + c4 * 256;
#pragma unroll 1
    for (int h = 0; h < 2; h++) {
        const float* BG = Bg4 + h * 128;
        u64 acc2[8][2] = {};
        GEMM_PASS(BG, CHUNK2);
#pragma unroll
        for (int i = 0; i < 8; i++) {
            float v0, v1, v2, v3;
            UNPACK64(v0, v1, acc2[i][0]);
            UNPACK64(v2, v3, acc2[i][1]);
            float4 s4 = *(const float4*)(g_S + qrow[i] * 256 + h * 128 + colg * 4);
            part[i] += v0 * s4.x + v1 * s4.y + v2 * s4.z + v3 * s4.w;
        }
        __syncthreads();   // Bs reuse between halves
    }

    // butterfly across 32 lanes (col groups) -> full 256-dot, write out once
#pragma unroll
    for (int i = 0; i < 8; i++) {
#pragma unroll
        for (int off = 16; off > 0; off >>= 1)
            part[i] += __shfl_xor_sync(0xffffffffu, part[i], off);
    }
    if (colg == 0) {
#pragma unroll
        for (int i = 0; i < 8; i++) {
            int l = base + sg * 8 + i;
            if (l < cnt) out[g_bkt[c * NS + l]] = part[i];
        }
    }
}

// ---------------------------------------------------------------------------
extern "C" void kernel_launch(void* const* d_in, const int* in_sizes, int n_in,
                              void* d_out, int out_size) {
    const float* core0 = (const float*)d_in[0];
    const float* core1 = (const float*)d_in[1];
    const float* core2 = (const float*)d_in[2];
    const float* core3 = (const float*)d_in[3];
    const float* core4 = (const float*)d_in[4];
    const float* core5 = (const float*)d_in[5];
    const float* core6 = (const float*)d_in[6];
    const float* core7 = (const float*)d_in[7];
    const int*   coords = (const int*)d_in[8];
    float* out = (float*)d_out;

    const int smem_fused = (8192 + 4096 + 32 * 260) * 4;   // 82432 B
    static bool attr_set = false;
    if (!attr_set) {
        cudaFuncSetAttribute(k_fused, cudaFuncAttributeMaxDynamicSharedMemorySize,
                             smem_fused);
        attr_set = true;
    }

    k_setup<<<80, 256>>>(core0, core1, core2, core5, core6, core7, coords);
    k_fused<<<FUSED_BLOCKS, 128, smem_fused>>>(core3, core4, out);
}

// round 13
// speedup vs baseline: 1.4677x; 1.4677x over previous
#include <cuda_runtime.h>

#define NS 4096
typedef unsigned long long u64;

// f32x2 packed math (sm_103a): one FFMA2 = 2 fp32 FMAs
#define PACKDUP(d, x)  asm("mov.b64 %0, {%1, %1};" : "=l"(d) : "f"(x))
#define FFMA2(d, a, b) asm("fma.rn.f32x2 %0, %1, %2, %0;" : "+l"(d) : "l"(a), "l"(b))
#define UNPACK64(lo, hi, v) asm("mov.b64 {%0, %1}, %2;" : "=f"(lo), "=f"(hi) : "l"(v))

// ---- scratch (device globals: no allocation allowed) ----
__device__ float g_P[512 * 256];     // prefix table  (c0,c1,c2)
__device__ float g_S[512 * 256];     // suffix table  (c5,c6,c7)
__device__ float g_V1[NS * 256];     // intermediate after level-3 GEMM
__device__ int   g_p[NS];
__device__ int   g_q[NS];
__device__ int   g_cnt3[8];          // zero-init at load; ticket re-zeros each run
__device__ int   g_cnt4[8];
__device__ int   g_b3[8 * NS];
__device__ int   g_b4[8 * NS];
__device__ int   g_done3;            // ticket counters for cleanup
__device__ int   g_done4;

#define GRID3 272                    // 136 x 2 halves
#define GRID4 272

// ---------------------------------------------------------------------------
// Fused setup: blocks 0-31 prefix GEMMs, 32-63 suffix GEMMs, 64-79 decode+zero.
__global__ void __launch_bounds__(256) k_setup(
    const float* __restrict__ c0, const float* __restrict__ c1,
    const float* __restrict__ c2, const float* __restrict__ c5,
    const float* __restrict__ c6, const float* __restrict__ c7,
    const int*   __restrict__ coords, float* __restrict__ out)
{
    __shared__ float sA[64 * 68];
    __shared__ float sB[64 * 68];
    int bid = blockIdx.x;
    int tid = threadIdx.x;

    if (bid < 32) {
        // ---------------- prefix: P[(ab,c)][col] = T[ab] @ core2[:,c,col] ----
        int cdig = bid >> 2, col0 = (bid & 3) * 64;
        for (int e = tid; e < 4096; e += 256) {
            int r = e >> 6, ab = e & 63;
            int a = ab >> 3, b = ab & 7;
            float acc = 0.f;
#pragma unroll
            for (int i = 0; i < 8; i++)
                acc += c0[a * 8 + i] * c1[(i * 8 + b) * 64 + r];
            sA[r * 68 + ab] = acc;
        }
        for (int e = tid; e < 4096; e += 256) {
            int r = e >> 6, cc = e & 63;
            sB[r * 68 + cc] = c2[(r * 8 + cdig) * 256 + col0 + cc];
        }
        __syncthreads();
        int ct = tid & 15, abt = tid >> 4;
        float acc[4][4] = {};
        for (int r = 0; r < 64; r++) {
            float4 tv = *(const float4*)&sA[r * 68 + abt * 4];
            float4 bv = *(const float4*)&sB[r * 68 + ct * 4];
            acc[0][0] += tv.x * bv.x; acc[0][1] += tv.x * bv.y; acc[0][2] += tv.x * bv.z; acc[0][3] += tv.x * bv.w;
            acc[1][0] += tv.y * bv.x; acc[1][1] += tv.y * bv.y; acc[1][2] += tv.y * bv.z; acc[1][3] += tv.y * bv.w;
            acc[2][0] += tv.z * bv.x; acc[2][1] += tv.z * bv.y; acc[2][2] += tv.z * bv.z; acc[2][3] += tv.z * bv.w;
            acc[3][0] += tv.w * bv.x; acc[3][1] += tv.w * bv.y; acc[3][2] += tv.w * bv.z; acc[3][3] += tv.w * bv.w;
        }
#pragma unroll
        for (int ii = 0; ii < 4; ii++) {
            int p = (abt * 4 + ii) * 8 + cdig;
            *(float4*)&g_P[p * 256 + col0 + ct * 4] =
                make_float4(acc[ii][0], acc[ii][1], acc[ii][2], acc[ii][3]);
        }
    } else if (bid < 64) {
        // ---------------- suffix: S[(a,bc)][row] = core5[row,a,:] @ U[bc] ----
        int b2 = bid - 32;
        int adig = b2 >> 2, row0 = (b2 & 3) * 64;
        for (int e = tid; e < 4096; e += 256) {
            int r = e >> 6, j = e & 63;
            sA[j * 68 + r] = c5[((row0 + r) * 8 + adig) * 64 + j];
        }
        for (int e = tid; e < 4096; e += 256) {
            int j = e >> 6, bc = e & 63;
            int b = bc >> 3, c = bc & 7;
            float acc = 0.f;
#pragma unroll
            for (int i = 0; i < 8; i++)
                acc += c6[(j * 8 + b) * 8 + i] * c7[i * 8 + c];
            sB[j * 68 + bc] = acc;
        }
        __syncthreads();
        int rt = tid & 15, bct = tid >> 4;
        float acc[4][4] = {};
        for (int j = 0; j < 64; j++) {
            float4 av = *(const float4*)&sA[j * 68 + rt * 4];
            float4 uv = *(const float4*)&sB[j * 68 + bct * 4];
            acc[0][0] += av.x * uv.x; acc[0][1] += av.x * uv.y; acc[0][2] += av.x * uv.z; acc[0][3] += av.x * uv.w;
            acc[1][0] += av.y * uv.x; acc[1][1] += av.y * uv.y; acc[1][2] += av.y * uv.z; acc[1][3] += av.y * uv.w;
            acc[2][0] += av.z * uv.x; acc[2][1] += av.z * uv.y; acc[2][2] += av.z * uv.z; acc[2][3] += av.z * uv.w;
            acc[3][0] += av.w * uv.x; acc[3][1] += av.w * uv.y; acc[3][2] += av.w * uv.z; acc[3][3] += av.w * uv.w;
        }
#pragma unroll
        for (int jj = 0; jj < 4; jj++) {
            int q = adig * 64 + bct * 4 + jj;
            *(float4*)&g_S[q * 256 + row0 + rt * 4] =
                make_float4(acc[0][jj], acc[1][jj], acc[2][jj], acc[3][jj]);
        }
    } else {
        // ---------------- decode + zero out ----------------
        int n = (bid - 64) * 256 + tid;
        if (n < NS) {
            out[n] = 0.f;   // gemm4 halves accumulate via atomicAdd
            int x = coords[3 * n], y = coords[3 * n + 1], z = coords[3 * n + 2];
            int d[8];
#pragma unroll
            for (int l = 0; l < 8; l++) {
                int sh = 7 - l;
                d[l] = 4 * ((x >> sh) & 1) + 2 * ((y >> sh) & 1) + ((z >> sh) & 1);
            }
            g_p[n] = d[0] * 64 + d[1] * 8 + d[2];
            g_q[n] = d[5] * 64 + d[6] * 8 + d[7];
            int pos3 = atomicAdd(&g_cnt3[d[3]], 1);
            g_b3[d[3] * NS + pos3] = n;
            int pos4 = atomicAdd(&g_cnt4[d[4]], 1);
            g_b4[d[4] * NS + pos4] = n;
        }
    }
}

// ---------------------------------------------------------------------------
// Pipelined FFMA2 GEMM: 32 samples x 128 cols (half = blockIdx.y), K=256.
// 128 threads: colg = tid&31 (4 cols), sg = tid>>5 (8 samples = 4 packed pairs).
// K in 8 chunks of 32 rows; double-buffered Bs -> ONE barrier per chunk:
// iteration kc: LDB(kc+1) -> regs, compute chunk kc from buf[kc&1],
// store regs to buf[(kc+1)&1] (other buffer, no hazard), sync.
// Shared = Ast[256][32] 32KB + Bs[2][32][128] 32KB = 64KB -> 3 blocks/SM.

__device__ __forceinline__ int2 tile_map(const int* __restrict__ cnt, int t) {
    int acc = 0, c = -1, base = 0;
#pragma unroll
    for (int i = 0; i < 8; i++) {
        int tiles = (cnt[i] + 31) >> 5;
        if (c < 0 && t < acc + tiles) { c = i; base = (t - acc) * 32; }
        acc += tiles;
    }
    return make_int2(c, base);
}

// ticket cleanup: after ALL blocks of this grid have read the counters,
// the last arrival zeroes them (ready for next graph replay).
#define TICKET_CLEAN(DONE, CNT, TOTAL)                                         \
    {                                                                          \
        __syncthreads();                                                       \
        if (tid == 0) {                                                        \
            int old = atomicAdd(&DONE, 1);                                     \
            if (old == (TOTAL) - 1) {                                          \
                _Pragma("unroll")                                              \
                for (int j = 0; j < 8; j++) CNT[j] = 0;                        \
                DONE = 0;                                                      \
            }                                                                  \
        }                                                                      \
    }

#define LDB(KC)                                                                \
    {                                                                          \
        _Pragma("unroll")                                                      \
        for (int p4 = 0; p4 < 8; p4++)                                         \
            nb[p4] = __ldg((const float4*)(Bg + ((KC) * 32 + p4 * 4 + brow) * 2048 + bcol)); \
    }
#define STB(BUF)                                                               \
    {                                                                          \
        _Pragma("unroll")                                                      \
        for (int p4 = 0; p4 < 8; p4++)                                         \
            *(float4*)&Bs[(BUF) * 4096 + (p4 * 4 + brow) * 128 + bcol] = nb[p4]; \
    }
#define CHUNK_COMPUTE(KC, BUF)                                                 \
    {                                                                          \
        _Pragma("unroll 8")                                                    \
        for (int kk = 0; kk < 32; kk++) {                                      \
            float4 b = *(const float4*)&Bs[(BUF) * 4096 + kk * 128 + colg * 4]; \
            u64 bd0, bd1, bd2, bd3;                                            \
            PACKDUP(bd0, b.x); PACKDUP(bd1, b.y);                              \
            PACKDUP(bd2, b.z); PACKDUP(bd3, b.w);                              \
            const u64* ap = (const u64*)&Ast[((KC) * 32 + kk) * 32 + sg * 8];  \
            u64 a0 = ap[0], a1 = ap[1], a2 = ap[2], a3 = ap[3];                \
            FFMA2(acc[0][0], a0, bd0); FFMA2(acc[0][1], a0, bd1);              \
            FFMA2(acc[0][2], a0, bd2); FFMA2(acc[0][3], a0, bd3);              \
            FFMA2(acc[1][0], a1, bd0); FFMA2(acc[1][1], a1, bd1);              \
            FFMA2(acc[1][2], a1, bd2); FFMA2(acc[1][3], a1, bd3);              \
            FFMA2(acc[2][0], a2, bd0); FFMA2(acc[2][1], a2, bd1);              \
            FFMA2(acc[2][2], a2, bd2); FFMA2(acc[2][3], a2, bd3);              \
            FFMA2(acc[3][0], a3, bd0); FFMA2(acc[3][1], a3, bd1);              \
            FFMA2(acc[3][2], a3, bd2); FFMA2(acc[3][3], a3, bd3);              \
        }                                                                      \
    }
#define GEMM_MAIN()                                                            \
    LDB(0); STB(0); __syncthreads();                                           \
    _Pragma("unroll 1")                                                        \
    for (int kc = 0; kc < 8; kc++) {                                           \
        if (kc < 7) LDB(kc + 1);                                               \
        CHUNK_COMPUTE(kc, kc & 1);                                             \
        if (kc < 7) { STB((kc + 1) & 1); __syncthreads(); }                    \
    }

// A staging (transposed): thread owns sample s = tid&31; 16 float4 passes.
#define STAGE_A(SRC, ROWSEL)                                                   \
    {                                                                          \
        int s = tid & 31;                                                      \
        int li = base + s;                                                     \
        int rsel = -1;                                                         \
        if (li < cnt) { int nn = ROWSEL; rsel = nn; }                          \
        _Pragma("unroll")                                                      \
        for (int pass = 0; pass < 16; pass++) {                                \
            int kq = (tid >> 5) + 4 * pass;                                    \
            float4 v = make_float4(0.f, 0.f, 0.f, 0.f);                        \
            if (rsel >= 0) v = __ldg((const float4*)(SRC + rsel * 256 + kq * 4)); \
            Ast[(kq * 4 + 0) * 32 + s] = v.x;                                  \
            Ast[(kq * 4 + 1) * 32 + s] = v.y;                                  \
            Ast[(kq * 4 + 2) * 32 + s] = v.z;                                  \
            Ast[(kq * 4 + 3) * 32 + s] = v.w;                                  \
        }                                                                      \
    }

// Level-3: V1[n, half] = P[p[n],:] @ core3[:,c, half-cols]
__global__ void __launch_bounds__(128) k_gemm3(const float* __restrict__ B) {
    __shared__ float Ast[256 * 32];
    __shared__ float Bs[2 * 32 * 128];
    int tid = threadIdx.x;
    int2 cb = tile_map(g_cnt3, blockIdx.x);
    int c = cb.x, base = cb.y;
    int cnt = (c >= 0) ? g_cnt3[c] : 0;
    TICKET_CLEAN(g_done3, g_cnt3, GRID3);
    if (c < 0) return;

    STAGE_A(g_P, g_p[g_b3[c * NS + li]]);
    __syncthreads();

    int half = blockIdx.y;
    int colg = tid & 31, sg = tid >> 5;
    int brow = tid >> 5, bcol = (tid & 31) * 4;
    const float* Bg = B + c * 256 + half * 128;
    float4 nb[8];
    u64 acc[4][4] = {};
    GEMM_MAIN();

#pragma unroll
    for (int p = 0; p < 4; p++) {
        float lo0, lo1, lo2, lo3, hi0, hi1, hi2, hi3;
        UNPACK64(lo0, hi0, acc[p][0]); UNPACK64(lo1, hi1, acc[p][1]);
        UNPACK64(lo2, hi2, acc[p][2]); UNPACK64(lo3, hi3, acc[p][3]);
        int l0 = base + sg * 8 + 2 * p, l1 = l0 + 1;
        int n0 = (l0 < cnt) ? g_b3[c * NS + l0] : -1;
        int n1 = (l1 < cnt) ? g_b3[c * NS + l1] : -1;
        if (n0 >= 0) *(float4*)&g_V1[n0 * 256 + half * 128 + colg * 4] =
            make_float4(lo0, lo1, lo2, lo3);
        if (n1 >= 0) *(float4*)&g_V1[n1 * 256 + half * 128 + colg * 4] =
            make_float4(hi0, hi1, hi2, hi3);
    }
}

// Level-4 + suffix dot: out[n] += (V1[n]@C4[c])[half] . S[q[n]][half]
__global__ void __launch_bounds__(128) k_gemm4(const float* __restrict__ B,
                                               float* __restrict__ out) {
    __shared__ float Ast[256 * 32];
    __shared__ float Bs[2 * 32 * 128];
    int tid = threadIdx.x;
    int2 cb = tile_map(g_cnt4, blockIdx.x);
    int c = cb.x, base = cb.y;
    int cnt = (c >= 0) ? g_cnt4[c] : 0;
    TICKET_CLEAN(g_done4, g_cnt4, GRID4);
    if (c < 0) return;

    STAGE_A(g_V1, g_b4[c * NS + li]);
    __syncthreads();

    int half = blockIdx.y;
    int colg = tid & 31, sg = tid >> 5;
    int brow = tid >> 5, bcol = (tid & 31) * 4;
    const float* Bg = B + c * 256 + half * 128;
    float4 nb[8];
    u64 acc[4][4] = {};
    GEMM_MAIN();

    // per-sample dot with suffix vector; butterfly over warp (32 colg = half)
    float part[8];
#pragma unroll
    for (int p = 0; p < 4; p++) {
        float lo0, lo1, lo2, lo3, hi0, hi1, hi2, hi3;
        UNPACK64(lo0, hi0, acc[p][0]); UNPACK64(lo1, hi1, acc[p][1]);
        UNPACK64(lo2, hi2, acc[p][2]); UNPACK64(lo3, hi3, acc[p][3]);
        int l0 = base + sg * 8 + 2 * p, l1 = l0 + 1;
        int nn0 = (l0 < cnt) ? g_b4[c * NS + l0] : -1;
        int nn1 = (l1 < cnt) ? g_b4[c * NS + l1] : -1;
        int q0 = (nn0 >= 0) ? g_q[nn0] : 0;
        int q1 = (nn1 >= 0) ? g_q[nn1] : 0;
        float4 s0 = *(const float4*)(g_S + q0 * 256 + half * 128 + colg * 4);
        float4 s1 = *(const float4*)(g_S + q1 * 256 + half * 128 + colg * 4);
        part[2 * p]     = lo0 * s0.x + lo1 * s0.y + lo2 * s0.z + lo3 * s0.w;
        part[2 * p + 1] = hi0 * s1.x + hi1 * s1.y + hi2 * s1.z + hi3 * s1.w;
    }
#pragma unroll
    for (int i = 0; i < 8; i++) {
#pragma unroll
        for (int off = 16; off > 0; off >>= 1)
            part[i] += __shfl_xor_sync(0xffffffffu, part[i], off);
    }
    if (colg == 0) {
        // two halves accumulate into out[n]; a+b == b+a bitwise -> deterministic
#pragma unroll
        for (int i = 0; i < 8; i++) {
            int l = base + sg * 8 + i;
            if (l < cnt) atomicAdd(out + g_b4[c * NS + l], part[i]);
        }
    }
}

// ---------------------------------------------------------------------------
extern "C" void kernel_launch(void* const* d_in, const int* in_sizes, int n_in,
                              void* d_out, int out_size) {
    const float* core0 = (const float*)d_in[0];
    const float* core1 = (const float*)d_in[1];
    const float* core2 = (const float*)d_in[2];
    const float* core3 = (const float*)d_in[3];
    const float* core4 = (const float*)d_in[4];
    const float* core5 = (const float*)d_in[5];
    const float* core6 = (const float*)d_in[6];
    const float* core7 = (const float*)d_in[7];
    const int*   coords = (const int*)d_in[8];
    float* out = (float*)d_out;

    k_setup<<<80, 256>>>(core0, core1, core2, core5, core6, core7, coords, out);
    k_gemm3<<<dim3(136, 2), 128>>>(core3);
    k_gemm4<<<dim3(136, 2), 128>>>(core4, out);
}